// round 15
// baseline (speedup 1.0000x reference)
#include <cuda_runtime.h>
#include <cuda_bf16.h>
#include <cuda_fp16.h>
#include <cstdint>

#define NN   100000
#define EE   1600000
#define KIN  256
#define KOUT 128
#define NB_SCAN ((NN + 1023) / 1024)   // 98

// Scratch (allocation-free rule: __device__ globals)
__device__ __half g_featproj[NN * KOUT];   // 25.6 MB projected features (fp16, UNSCALED)
__device__ float2 g_edges[EE];             // dst-bucketed (src_bits, w*outscale)
__device__ int    g_outcnt[NN];
__device__ int    g_incnt[NN];
__device__ int    g_scanpart[NN];
__device__ int    g_rowoff[NN + 1];
__device__ int    g_cursor[NN];
__device__ int    g_blocksum[NB_SCAN];
__device__ int    g_blockoff[NB_SCAN];
__device__ __nv_bfloat16 g_wt_hi[KOUT * KIN];   // W^T hi  [N=128][K=256]
__device__ __nv_bfloat16 g_wt_lo[KOUT * KIN];   // W^T lo

// ---------------------------------------------------------------------------
__global__ void k_init() {
    int i = blockIdx.x * blockDim.x + threadIdx.x;
    int stride = gridDim.x * blockDim.x;
    for (int j = i; j < NN; j += stride) { g_outcnt[j] = 0; g_incnt[j] = 0; }
    if (i == 0) g_rowoff[NN] = EE;
}

// ---------------------------------------------------------------------------
__global__ void k_deg(const int* __restrict__ src, const int* __restrict__ dst) {
    int i = blockIdx.x * blockDim.x + threadIdx.x;
    if (i < EE) {
        atomicAdd(&g_outcnt[src[i]], 1);
        atomicAdd(&g_incnt[dst[i]], 1);
    }
}

// ---------------------------------------------------------------------------
// Exclusive scan of in-degrees (3 kernels)
// ---------------------------------------------------------------------------
__device__ __forceinline__ int warpInclScan(int v) {
#pragma unroll
    for (int o = 1; o < 32; o <<= 1) {
        int n = __shfl_up_sync(0xFFFFFFFFu, v, o);
        if ((threadIdx.x & 31) >= o) v += n;
    }
    return v;
}

__global__ __launch_bounds__(1024) void k_scan1() {
    __shared__ int ws[32];
    int tid = threadIdx.x;
    int i = blockIdx.x * 1024 + tid;
    int lane = tid & 31, wid = tid >> 5;
    int v = (i < NN) ? g_incnt[i] : 0;
    int inc = warpInclScan(v);
    if (lane == 31) ws[wid] = inc;
    __syncthreads();
    if (wid == 0) ws[lane] = warpInclScan(ws[lane]);
    __syncthreads();
    int excl = inc - v + (wid > 0 ? ws[wid - 1] : 0);
    if (i < NN) g_scanpart[i] = excl;
    if (tid == 1023) g_blocksum[blockIdx.x] = ws[31];
}

__global__ __launch_bounds__(128) void k_scan2() {
    __shared__ int ws[4];
    int tid = threadIdx.x;
    int lane = tid & 31, wid = tid >> 5;
    int v = (tid < NB_SCAN) ? g_blocksum[tid] : 0;
    int inc = warpInclScan(v);
    if (lane == 31) ws[wid] = inc;
    __syncthreads();
    if (wid == 0) {
        int w = (lane < 4) ? ws[lane] : 0;   // full warp runs the shfl scan
        w = warpInclScan(w);
        if (lane < 4) ws[lane] = w;
    }
    __syncthreads();
    int excl = inc - v + (wid > 0 ? ws[wid - 1] : 0);
    if (tid < NB_SCAN) g_blockoff[tid] = excl;
}

__global__ void k_scan3() {
    int i = blockIdx.x * blockDim.x + threadIdx.x;
    if (i < NN) {
        int off = g_scanpart[i] + g_blockoff[i >> 10];
        g_rowoff[i] = off;
        g_cursor[i] = off;
    }
}

// ---------------------------------------------------------------------------
// Bucket edges by dst; fold out_deg^-1/2 of src into the edge weight so the
// GEMM has no dependency on degrees (stream overlap from t=0).
// ---------------------------------------------------------------------------
__global__ void k_bucket(const int* __restrict__ src, const int* __restrict__ dst,
                         const float* __restrict__ ew) {
    int e = blockIdx.x * blockDim.x + threadIdx.x;
    if (e < EE) {
        int s = src[e];
        int d = dst[e];
        float w = ew[e] * rsqrtf((float)max(g_outcnt[s], 1));
        int pos = atomicAdd(&g_cursor[d], 1);
        g_edges[pos] = make_float2(__int_as_float(s), w);
    }
}

// ---------------------------------------------------------------------------
// Kernel: transpose + mask + bf16 trunc-hi/lo split of weight: W[K,N]->Wt[N,K]
// ---------------------------------------------------------------------------
__global__ void k_wt(const float* __restrict__ weight, const float* __restrict__ maskr) {
    int i = blockIdx.x * blockDim.x + threadIdx.x;
    if (i >= KOUT * KIN) return;
    int n = i >> 8;          // 0..127
    int k = i & 255;         // 0..255
    float v = (maskr[k * KOUT + n] > 0.5f) ? weight[k * KOUT + n] : 0.f;
    uint32_t u = __float_as_uint(v);
    uint32_t hi_bits = u & 0xFFFF0000u;                 // truncation hi
    float lo = v - __uint_as_float(hi_bits);
    g_wt_hi[i] = __ushort_as_bfloat16((unsigned short)(hi_bits >> 16));
    g_wt_lo[i] = __float2bfloat16(lo);
}

// ---------------------------------------------------------------------------
// bf16-split tensor-core GEMM on mma.sync (HMMA), BM=64 for 3 CTAs/SM.
// featproj(fp16) = feat @ maskedW (UNSCALED; out-degree scale in edges).
// BM=64, BN=128, BK=32; 8 warps as 2m x 4n, warp tile 32x32.
// ---------------------------------------------------------------------------
#define SSTR 40

__device__ __forceinline__ uint32_t smem_u32(const void* p) {
    uint32_t a;
    asm("{ .reg .u64 t; cvta.to.shared.u64 t, %1; cvt.u32.u64 %0, t; }"
        : "=r"(a) : "l"(p));
    return a;
}

__device__ __forceinline__ void ldm_x4(uint32_t* r, uint32_t addr) {
    asm volatile("ldmatrix.sync.aligned.m8n8.x4.shared.b16 {%0,%1,%2,%3}, [%4];"
                 : "=r"(r[0]), "=r"(r[1]), "=r"(r[2]), "=r"(r[3]) : "r"(addr));
}

__device__ __forceinline__ void mma_bf16(float* c, const uint32_t* a, const uint32_t* b) {
    asm volatile(
        "mma.sync.aligned.m16n8k16.row.col.f32.bf16.bf16.f32 "
        "{%0,%1,%2,%3}, {%4,%5,%6,%7}, {%8,%9}, {%0,%1,%2,%3};"
        : "+f"(c[0]), "+f"(c[1]), "+f"(c[2]), "+f"(c[3])
        : "r"(a[0]), "r"(a[1]), "r"(a[2]), "r"(a[3]), "r"(b[0]), "r"(b[1]));
}

// split one pair of floats: packed trunc-hi bf16x2 + packed RN-lo bf16x2
__device__ __forceinline__ void split2(float f0, float f1,
                                       uint32_t& hi2, uint32_t& lo2) {
    uint32_t u0 = __float_as_uint(f0), u1 = __float_as_uint(f1);
    hi2 = __byte_perm(u0, u1, 0x7632);                  // {u0.hi16, u1.hi16}
    float l0 = f0 - __uint_as_float(u0 & 0xFFFF0000u);
    float l1 = f1 - __uint_as_float(u1 & 0xFFFF0000u);
    __nv_bfloat162 l = __floats2bfloat162_rn(l0, l1);
    lo2 = *reinterpret_cast<uint32_t*>(&l);
}

__global__ __launch_bounds__(256, 3) void k_gemm_mma(const float* __restrict__ feat) {
    __shared__ __nv_bfloat16 sAhi[64 * SSTR];
    __shared__ __nv_bfloat16 sAlo[64 * SSTR];
    __shared__ __nv_bfloat16 sBhi[128 * SSTR];
    __shared__ __nv_bfloat16 sBlo[128 * SSTR];

    const int tid = threadIdx.x;
    const int wid = tid >> 5, lane = tid & 31;
    const int blockRow = blockIdx.x * 64;

    const uint32_t uAhi = smem_u32(sAhi), uAlo = smem_u32(sAlo);
    const uint32_t uBhi = smem_u32(sBhi), uBlo = smem_u32(sBlo);

    // warp tile: 32 rows x 32 cols; 8 warps = 2m x 4n
    const int mbase = (wid & 1) * 32;
    const int nbase = (wid >> 1) * 32;

    float acc[2][4][4];
#pragma unroll
    for (int m = 0; m < 2; m++)
#pragma unroll
        for (int n = 0; n < 4; n++)
#pragma unroll
            for (int q = 0; q < 4; q++) acc[m][n][q] = 0.f;

    const uint32_t aoff = (uint32_t)((lane & 15) * (SSTR * 2) + (lane >> 4) * 16);
    const uint32_t boff = (uint32_t)(((lane & 7) + ((lane >> 4) << 3)) * (SSTR * 2) +
                                     (((lane >> 3) & 1) << 4));

    // A load mapping: 64 rows x 32 cols, 4 threads/row, 8 cols each
    const int arow = tid >> 2;
    const int ach  = (tid & 3) * 8;
    const int grow = blockRow + arow;
    const float4* apbase = (grow < NN)
        ? reinterpret_cast<const float4*>(&feat[grow * KIN + ach]) : nullptr;
    const int asm_off = arow * SSTR + ach;
    // B load mapping: 128 rows, 2 threads/row, 16 cols each
    const int brow = tid >> 1;
    const int bq = (tid & 1) * 2;
    const int bsm_off = brow * SSTR + bq * 8;

    // prologue: prefetch chunk 0 of A (2 float4 per thread)
    float4 pa[2];
#pragma unroll
    for (int j = 0; j < 2; j++)
        pa[j] = apbase ? apbase[j] : make_float4(0.f, 0.f, 0.f, 0.f);

    for (int c = 0; c < 8; c++) {
        const int k0 = c * 32;

        // ---- store stage: A split from prefetched regs
#pragma unroll
        for (int j = 0; j < 2; j++) {
            uint32_t h01, l01, h23, l23;
            split2(pa[j].x, pa[j].y, h01, l01);
            split2(pa[j].z, pa[j].w, h23, l23);
            int o = asm_off + j * 4;
            *reinterpret_cast<uint2*>(&sAhi[o]) = make_uint2(h01, h23);
            *reinterpret_cast<uint2*>(&sAlo[o]) = make_uint2(l01, l23);
        }
        // ---- B from L2-resident g_wt
        {
            uint4 h0 = *reinterpret_cast<const uint4*>(&g_wt_hi[brow * KIN + k0 + bq * 8]);
            uint4 h1 = *reinterpret_cast<const uint4*>(&g_wt_hi[brow * KIN + k0 + (bq + 1) * 8]);
            uint4 l0 = *reinterpret_cast<const uint4*>(&g_wt_lo[brow * KIN + k0 + bq * 8]);
            uint4 l1 = *reinterpret_cast<const uint4*>(&g_wt_lo[brow * KIN + k0 + (bq + 1) * 8]);
            *reinterpret_cast<uint4*>(&sBhi[bsm_off])     = h0;
            *reinterpret_cast<uint4*>(&sBhi[bsm_off + 8]) = h1;
            *reinterpret_cast<uint4*>(&sBlo[bsm_off])     = l0;
            *reinterpret_cast<uint4*>(&sBlo[bsm_off + 8]) = l1;
        }
        __syncthreads();

        // ---- prefetch next chunk's A (latency hides under MMAs below)
        if (c < 7) {
            const float4* ap = apbase ? apbase + (c + 1) * 8 : nullptr;
#pragma unroll
            for (int j = 0; j < 2; j++)
                pa[j] = ap ? ap[j] : make_float4(0.f, 0.f, 0.f, 0.f);
        }

        // ---- MMA stage
#pragma unroll
        for (int ks = 0; ks < 2; ks++) {
            const uint32_t kb = (uint32_t)(ks * 16 * 2);

            uint32_t ahi[2][4], alo[2][4];
#pragma unroll
            for (int mt = 0; mt < 2; mt++) {
                uint32_t ab = (uint32_t)((mbase + mt * 16) * (SSTR * 2)) + kb + aoff;
                ldm_x4(ahi[mt], uAhi + ab);
                ldm_x4(alo[mt], uAlo + ab);
            }
#pragma unroll
            for (int p = 0; p < 2; p++) {
                uint32_t bb = (uint32_t)((nbase + p * 16) * (SSTR * 2)) + kb + boff;
                uint32_t rh[4], rl[4];
                ldm_x4(rh, uBhi + bb);
                ldm_x4(rl, uBlo + bb);
#pragma unroll
                for (int mt = 0; mt < 2; mt++) {
                    mma_bf16(acc[mt][2 * p],     ahi[mt], rh);
                    mma_bf16(acc[mt][2 * p],     ahi[mt], rl);
                    mma_bf16(acc[mt][2 * p],     alo[mt], rh);
                    mma_bf16(acc[mt][2 * p + 1], ahi[mt], rh + 2);
                    mma_bf16(acc[mt][2 * p + 1], ahi[mt], rl + 2);
                    mma_bf16(acc[mt][2 * p + 1], alo[mt], rh + 2);
                }
            }
        }
        __syncthreads();
    }

    // Epilogue: store fp16 result
#pragma unroll
    for (int mt = 0; mt < 2; mt++) {
        int r0 = blockRow + mbase + mt * 16 + (lane >> 2);
        int r1 = r0 + 8;
#pragma unroll
        for (int nt = 0; nt < 4; nt++) {
            int col = nbase + nt * 8 + (lane & 3) * 2;
            if (r0 < NN)
                *reinterpret_cast<__half2*>(&g_featproj[r0 * KOUT + col]) =
                    __floats2half2_rn(acc[mt][nt][0], acc[mt][nt][1]);
            if (r1 < NN)
                *reinterpret_cast<__half2*>(&g_featproj[r1 * KOUT + col]) =
                    __floats2half2_rn(acc[mt][nt][2], acc[mt][nt][3]);
        }
    }
}

// ---------------------------------------------------------------------------
// Kernel: aggregation. One warp per dst node; fp16 gathers (256B/edge-warp),
// fp32 accumulation, fused in_deg^-1/2 + bias. No fp atomics.
// ---------------------------------------------------------------------------
__global__ __launch_bounds__(256) void k_agg(float* __restrict__ out,
                                             const float* __restrict__ bias) {
    int node = blockIdx.x * 8 + (threadIdx.x >> 5);
    int lane = threadIdx.x & 31;
    if (node >= NN) return;

    int beg = g_rowoff[node];
    int end = g_rowoff[node + 1];

    float4 acc = make_float4(0.f, 0.f, 0.f, 0.f);
    int e = beg;
    for (; e + 1 < end; e += 2) {
        float2 e0 = g_edges[e];
        float2 e1 = g_edges[e + 1];
        int s0 = __float_as_int(e0.x);
        int s1 = __float_as_int(e1.x);
        uint2 q0 = *reinterpret_cast<const uint2*>(&g_featproj[s0 * KOUT + lane * 4]);
        uint2 q1 = *reinterpret_cast<const uint2*>(&g_featproj[s1 * KOUT + lane * 4]);
        float2 a0 = __half22float2(*reinterpret_cast<__half2*>(&q0.x));
        float2 b0 = __half22float2(*reinterpret_cast<__half2*>(&q0.y));
        float2 a1 = __half22float2(*reinterpret_cast<__half2*>(&q1.x));
        float2 b1 = __half22float2(*reinterpret_cast<__half2*>(&q1.y));
        acc.x = fmaf(e0.y, a0.x, fmaf(e1.y, a1.x, acc.x));
        acc.y = fmaf(e0.y, a0.y, fmaf(e1.y, a1.y, acc.y));
        acc.z = fmaf(e0.y, b0.x, fmaf(e1.y, b1.x, acc.z));
        acc.w = fmaf(e0.y, b0.y, fmaf(e1.y, b1.y, acc.w));
    }
    if (e < end) {
        float2 e0 = g_edges[e];
        int s0 = __float_as_int(e0.x);
        uint2 q0 = *reinterpret_cast<const uint2*>(&g_featproj[s0 * KOUT + lane * 4]);
        float2 a0 = __half22float2(*reinterpret_cast<__half2*>(&q0.x));
        float2 b0 = __half22float2(*reinterpret_cast<__half2*>(&q0.y));
        acc.x = fmaf(e0.y, a0.x, acc.x);
        acc.y = fmaf(e0.y, a0.y, acc.y);
        acc.z = fmaf(e0.y, b0.x, acc.z);
        acc.w = fmaf(e0.y, b0.y, acc.w);
    }

    float sc = rsqrtf((float)max(end - beg, 1));
    float4 b = *reinterpret_cast<const float4*>(&bias[lane * 4]);
    acc.x = fmaf(acc.x, sc, b.x);
    acc.y = fmaf(acc.y, sc, b.y);
    acc.z = fmaf(acc.z, sc, b.z);
    acc.w = fmaf(acc.w, sc, b.w);
    *reinterpret_cast<float4*>(&out[node * KOUT + lane * 4]) = acc;
}

// ---------------------------------------------------------------------------
// Fork-join with valid capture semantics: fork event recorded on the capturing
// stream BEFORE any side-stream work; side stream joins capture via WaitEvent.
// ---------------------------------------------------------------------------
static cudaStream_t s_side = 0;
static cudaEvent_t  s_eFork = 0, s_eGemm = 0;

extern "C" void kernel_launch(void* const* d_in, const int* in_sizes, int n_in,
                              void* d_out, int out_size) {
    const float* feat   = (const float*)d_in[0];
    const int*   src    = (const int*)  d_in[1];
    const int*   dst    = (const int*)  d_in[2];
    const float* ew     = (const float*)d_in[3];
    const float* weight = (const float*)d_in[4];
    const float* bias   = (const float*)d_in[5];
    const float* maskr  = (const float*)d_in[6];
    float* out = (float*)d_out;

    if (!s_side) {
        cudaStreamCreateWithFlags(&s_side, cudaStreamNonBlocking);
        cudaEventCreateWithFlags(&s_eFork, cudaEventDisableTiming);
        cudaEventCreateWithFlags(&s_eGemm, cudaEventDisableTiming);
    }

    // fork: event on the capturing (default) stream, side stream waits on it
    cudaEventRecord(s_eFork, 0);
    cudaStreamWaitEvent(s_side, s_eFork, 0);

    // side stream: weight split + GEMM (no degree dependency)
    k_wt<<<(KOUT * KIN + 255) / 256, 256, 0, s_side>>>(weight, maskr);
    k_gemm_mma<<<(NN + 63) / 64, 256, 0, s_side>>>(feat);
    cudaEventRecord(s_eGemm, s_side);

    // main stream: degrees + CSR build
    k_init<<<256, 256>>>();
    k_deg<<<(EE + 255) / 256, 256>>>(src, dst);
    k_scan1<<<NB_SCAN, 1024>>>();
    k_scan2<<<1, 128>>>();
    k_scan3<<<(NN + 255) / 256, 256>>>();
    k_bucket<<<(EE + 255) / 256, 256>>>(src, dst, ew);

    // join, then aggregate
    cudaStreamWaitEvent(0, s_eGemm, 0);
    k_agg<<<(NN + 7) / 8, 256>>>(out, bias);
}

// round 16
// speedup vs baseline: 1.2218x; 1.2218x over previous
#include <cuda_runtime.h>
#include <cuda_fp16.h>
#include <cstdint>

#define NN   100000
#define EE   1600000
#define KIN  256
#define KOUT 128
#define NB_SCAN ((NN + 1023) / 1024)   // 98

// Scratch (allocation-free rule: __device__ globals)
__device__ __half g_featproj[NN * KOUT];   // 25.6 MB projected features (fp16, UNSCALED)
__device__ float2 g_edges[EE];             // dst-bucketed (src_bits, w*outscale)
__device__ int    g_outcnt[NN];
__device__ int    g_incnt[NN];
__device__ int    g_scanpart[NN];
__device__ int    g_rowoff[NN + 1];
__device__ int    g_cursor[NN];
__device__ int    g_blocksum[NB_SCAN];
__device__ int    g_blockoff[NB_SCAN];
__device__ __half g_wt[KOUT * KIN];        // W^T fp16(rn)  [N=128][K=256]

// ---------------------------------------------------------------------------
__global__ void k_init() {
    int i = blockIdx.x * blockDim.x + threadIdx.x;
    int stride = gridDim.x * blockDim.x;
    for (int j = i; j < NN; j += stride) { g_outcnt[j] = 0; g_incnt[j] = 0; }
    if (i == 0) g_rowoff[NN] = EE;
}

// ---------------------------------------------------------------------------
__global__ void k_deg(const int* __restrict__ src, const int* __restrict__ dst) {
    int i = blockIdx.x * blockDim.x + threadIdx.x;
    if (i < EE) {
        atomicAdd(&g_outcnt[src[i]], 1);
        atomicAdd(&g_incnt[dst[i]], 1);
    }
}

// ---------------------------------------------------------------------------
// Exclusive scan of in-degrees (3 kernels)
// ---------------------------------------------------------------------------
__device__ __forceinline__ int warpInclScan(int v) {
#pragma unroll
    for (int o = 1; o < 32; o <<= 1) {
        int n = __shfl_up_sync(0xFFFFFFFFu, v, o);
        if ((threadIdx.x & 31) >= o) v += n;
    }
    return v;
}

__global__ __launch_bounds__(1024) void k_scan1() {
    __shared__ int ws[32];
    int tid = threadIdx.x;
    int i = blockIdx.x * 1024 + tid;
    int lane = tid & 31, wid = tid >> 5;
    int v = (i < NN) ? g_incnt[i] : 0;
    int inc = warpInclScan(v);
    if (lane == 31) ws[wid] = inc;
    __syncthreads();
    if (wid == 0) ws[lane] = warpInclScan(ws[lane]);
    __syncthreads();
    int excl = inc - v + (wid > 0 ? ws[wid - 1] : 0);
    if (i < NN) g_scanpart[i] = excl;
    if (tid == 1023) g_blocksum[blockIdx.x] = ws[31];
}

__global__ __launch_bounds__(128) void k_scan2() {
    __shared__ int ws[4];
    int tid = threadIdx.x;
    int lane = tid & 31, wid = tid >> 5;
    int v = (tid < NB_SCAN) ? g_blocksum[tid] : 0;
    int inc = warpInclScan(v);
    if (lane == 31) ws[wid] = inc;
    __syncthreads();
    if (wid == 0) {
        int w = (lane < 4) ? ws[lane] : 0;   // full warp runs the shfl scan
        w = warpInclScan(w);
        if (lane < 4) ws[lane] = w;
    }
    __syncthreads();
    int excl = inc - v + (wid > 0 ? ws[wid - 1] : 0);
    if (tid < NB_SCAN) g_blockoff[tid] = excl;
}

__global__ void k_scan3() {
    int i = blockIdx.x * blockDim.x + threadIdx.x;
    if (i < NN) {
        int off = g_scanpart[i] + g_blockoff[i >> 10];
        g_rowoff[i] = off;
        g_cursor[i] = off;
    }
}

// ---------------------------------------------------------------------------
// Bucket edges by dst; fold out_deg^-1/2 of src into the edge weight so the
// GEMM has no dependency on degrees (stream overlap from t=0).
// ---------------------------------------------------------------------------
__global__ void k_bucket(const int* __restrict__ src, const int* __restrict__ dst,
                         const float* __restrict__ ew) {
    int e = blockIdx.x * blockDim.x + threadIdx.x;
    if (e < EE) {
        int s = src[e];
        int d = dst[e];
        float w = ew[e] * rsqrtf((float)max(g_outcnt[s], 1));
        int pos = atomicAdd(&g_cursor[d], 1);
        g_edges[pos] = make_float2(__int_as_float(s), w);
    }
}

// ---------------------------------------------------------------------------
// Kernel: transpose + mask + fp16(rn) of the weight: W[K,N] -> Wt[N,K]
// ---------------------------------------------------------------------------
__global__ void k_wt(const float* __restrict__ weight, const float* __restrict__ maskr) {
    int i = blockIdx.x * blockDim.x + threadIdx.x;
    if (i >= KOUT * KIN) return;
    int n = i >> 8;          // 0..127
    int k = i & 255;         // 0..255
    float v = (maskr[k * KOUT + n] > 0.5f) ? weight[k * KOUT + n] : 0.f;
    g_wt[i] = __float2half_rn(v);
}

// ---------------------------------------------------------------------------
// fp16 2-term tensor-core GEMM on mma.sync (HMMA).
// featproj(fp16) = feat @ maskedW via (Ahi + Alo)·B, fp32 accumulation.
// A: fp16 rn hi + rn residual lo. B: single fp16 rn.
// BM=128, BN=128, BK=32; 8 warps, warp tile 32x64. A-prefetch pipeline.
// ---------------------------------------------------------------------------
#define SSTR 40

__device__ __forceinline__ uint32_t smem_u32(const void* p) {
    uint32_t a;
    asm("{ .reg .u64 t; cvta.to.shared.u64 t, %1; cvt.u32.u64 %0, t; }"
        : "=r"(a) : "l"(p));
    return a;
}

__device__ __forceinline__ void ldm_x4(uint32_t* r, uint32_t addr) {
    asm volatile("ldmatrix.sync.aligned.m8n8.x4.shared.b16 {%0,%1,%2,%3}, [%4];"
                 : "=r"(r[0]), "=r"(r[1]), "=r"(r[2]), "=r"(r[3]) : "r"(addr));
}

__device__ __forceinline__ void mma_f16(float* c, const uint32_t* a, const uint32_t* b) {
    asm volatile(
        "mma.sync.aligned.m16n8k16.row.col.f32.f16.f16.f32 "
        "{%0,%1,%2,%3}, {%4,%5,%6,%7}, {%8,%9}, {%0,%1,%2,%3};"
        : "+f"(c[0]), "+f"(c[1]), "+f"(c[2]), "+f"(c[3])
        : "r"(a[0]), "r"(a[1]), "r"(a[2]), "r"(a[3]), "r"(b[0]), "r"(b[1]));
}

// split one pair of floats: packed rn-hi fp16x2 + packed rn-residual fp16x2
__device__ __forceinline__ void split2h(float f0, float f1,
                                        uint32_t& hi2, uint32_t& lo2) {
    __half2 h = __floats2half2_rn(f0, f1);
    float l0 = f0 - __low2float(h);
    float l1 = f1 - __high2float(h);
    __half2 l = __floats2half2_rn(l0, l1);
    hi2 = *reinterpret_cast<uint32_t*>(&h);
    lo2 = *reinterpret_cast<uint32_t*>(&l);
}

__global__ __launch_bounds__(256, 2) void k_gemm_mma(const float* __restrict__ feat) {
    __shared__ __half sAhi[128 * SSTR];
    __shared__ __half sAlo[128 * SSTR];
    __shared__ __half sB  [128 * SSTR];

    const int tid = threadIdx.x;
    const int wid = tid >> 5, lane = tid & 31;
    const int blockRow = blockIdx.x * 128;

    const uint32_t uAhi = smem_u32(sAhi), uAlo = smem_u32(sAlo);
    const uint32_t uB = smem_u32(sB);

    const int mbase = (wid & 3) * 32;
    const int nbase = (wid >> 2) * 64;

    float acc[2][8][4];
#pragma unroll
    for (int m = 0; m < 2; m++)
#pragma unroll
        for (int n = 0; n < 8; n++)
#pragma unroll
            for (int q = 0; q < 4; q++) acc[m][n][q] = 0.f;

    const uint32_t aoff = (uint32_t)((lane & 15) * (SSTR * 2) + (lane >> 4) * 16);
    const uint32_t boff = (uint32_t)(((lane & 7) + ((lane >> 4) << 3)) * (SSTR * 2) +
                                     (((lane >> 3) & 1) << 4));

    // per-thread load mappings
    const int arow = tid >> 1;
    const int ach  = (tid & 1) * 16;
    const int grow = blockRow + arow;
    const float4* apbase = (grow < NN)
        ? reinterpret_cast<const float4*>(&feat[grow * KIN + ach]) : nullptr;
    const int bq = (tid & 1) * 2;
    const int asm_off = arow * SSTR + ach;      // A smem elem offset
    const int bsm_off = arow * SSTR + bq * 8;   // B smem elem offset

    // prologue: prefetch chunk 0 of A
    float4 pa[4];
#pragma unroll
    for (int j = 0; j < 4; j++)
        pa[j] = apbase ? apbase[j] : make_float4(0.f, 0.f, 0.f, 0.f);

    for (int c = 0; c < 8; c++) {
        const int k0 = c * 32;

        // ---- store stage: A split from prefetched regs
#pragma unroll
        for (int j = 0; j < 4; j++) {
            uint32_t h01, l01, h23, l23;
            split2h(pa[j].x, pa[j].y, h01, l01);
            split2h(pa[j].z, pa[j].w, h23, l23);
            int o = asm_off + j * 4;
            *reinterpret_cast<uint2*>(&sAhi[o]) = make_uint2(h01, h23);
            *reinterpret_cast<uint2*>(&sAlo[o]) = make_uint2(l01, l23);
        }
        // ---- B (single fp16 buffer) from L2-resident g_wt
        {
            uint4 b0 = *reinterpret_cast<const uint4*>(&g_wt[arow * KIN + k0 + bq * 8]);
            uint4 b1 = *reinterpret_cast<const uint4*>(&g_wt[arow * KIN + k0 + (bq + 1) * 8]);
            *reinterpret_cast<uint4*>(&sB[bsm_off])     = b0;
            *reinterpret_cast<uint4*>(&sB[bsm_off + 8]) = b1;
        }
        __syncthreads();

        // ---- prefetch next chunk's A (DRAM latency hides under MMAs below)
        if (c < 7) {
            const float4* ap = apbase ? apbase + (c + 1) * 8 : nullptr;
#pragma unroll
            for (int j = 0; j < 4; j++)
                pa[j] = ap ? ap[j] : make_float4(0.f, 0.f, 0.f, 0.f);
        }

        // ---- MMA stage: 2 terms (Ahi·B + Alo·B)
#pragma unroll
        for (int ks = 0; ks < 2; ks++) {
            const uint32_t kb = (uint32_t)(ks * 16 * 2);

            uint32_t ahi[2][4], alo[2][4];
#pragma unroll
            for (int mt = 0; mt < 2; mt++) {
                uint32_t ab = (uint32_t)((mbase + mt * 16) * (SSTR * 2)) + kb + aoff;
                ldm_x4(ahi[mt], uAhi + ab);
                ldm_x4(alo[mt], uAlo + ab);
            }
#pragma unroll
            for (int p = 0; p < 4; p++) {
                uint32_t bb = (uint32_t)((nbase + p * 16) * (SSTR * 2)) + kb + boff;
                uint32_t rb[4];
                ldm_x4(rb, uB + bb);
#pragma unroll
                for (int mt = 0; mt < 2; mt++) {
                    mma_f16(acc[mt][2 * p],     ahi[mt], rb);
                    mma_f16(acc[mt][2 * p],     alo[mt], rb);
                    mma_f16(acc[mt][2 * p + 1], ahi[mt], rb + 2);
                    mma_f16(acc[mt][2 * p + 1], alo[mt], rb + 2);
                }
            }
        }
        __syncthreads();
    }

    // Epilogue: store fp16 result
#pragma unroll
    for (int mt = 0; mt < 2; mt++) {
        int r0 = blockRow + mbase + mt * 16 + (lane >> 2);
        int r1 = r0 + 8;
#pragma unroll
        for (int nt = 0; nt < 8; nt++) {
            int col = nbase + nt * 8 + (lane & 3) * 2;
            if (r0 < NN)
                *reinterpret_cast<__half2*>(&g_featproj[r0 * KOUT + col]) =
                    __floats2half2_rn(acc[mt][nt][0], acc[mt][nt][1]);
            if (r1 < NN)
                *reinterpret_cast<__half2*>(&g_featproj[r1 * KOUT + col]) =
                    __floats2half2_rn(acc[mt][nt][2], acc[mt][nt][3]);
        }
    }
}

// ---------------------------------------------------------------------------
// Kernel: aggregation. One warp per dst node; fp16 gathers (256B/edge-warp),
// fp32 accumulation, fused in_deg^-1/2 + bias. No fp atomics.
// ---------------------------------------------------------------------------
__global__ __launch_bounds__(256) void k_agg(float* __restrict__ out,
                                             const float* __restrict__ bias) {
    int node = blockIdx.x * 8 + (threadIdx.x >> 5);
    int lane = threadIdx.x & 31;
    if (node >= NN) return;

    int beg = g_rowoff[node];
    int end = g_rowoff[node + 1];

    float4 acc = make_float4(0.f, 0.f, 0.f, 0.f);
    int e = beg;
    for (; e + 1 < end; e += 2) {
        float2 e0 = g_edges[e];
        float2 e1 = g_edges[e + 1];
        int s0 = __float_as_int(e0.x);
        int s1 = __float_as_int(e1.x);
        uint2 q0 = *reinterpret_cast<const uint2*>(&g_featproj[s0 * KOUT + lane * 4]);
        uint2 q1 = *reinterpret_cast<const uint2*>(&g_featproj[s1 * KOUT + lane * 4]);
        float2 a0 = __half22float2(*reinterpret_cast<__half2*>(&q0.x));
        float2 b0 = __half22float2(*reinterpret_cast<__half2*>(&q0.y));
        float2 a1 = __half22float2(*reinterpret_cast<__half2*>(&q1.x));
        float2 b1 = __half22float2(*reinterpret_cast<__half2*>(&q1.y));
        acc.x = fmaf(e0.y, a0.x, fmaf(e1.y, a1.x, acc.x));
        acc.y = fmaf(e0.y, a0.y, fmaf(e1.y, a1.y, acc.y));
        acc.z = fmaf(e0.y, b0.x, fmaf(e1.y, b1.x, acc.z));
        acc.w = fmaf(e0.y, b0.y, fmaf(e1.y, b1.y, acc.w));
    }
    if (e < end) {
        float2 e0 = g_edges[e];
        int s0 = __float_as_int(e0.x);
        uint2 q0 = *reinterpret_cast<const uint2*>(&g_featproj[s0 * KOUT + lane * 4]);
        float2 a0 = __half22float2(*reinterpret_cast<__half2*>(&q0.x));
        float2 b0 = __half22float2(*reinterpret_cast<__half2*>(&q0.y));
        acc.x = fmaf(e0.y, a0.x, acc.x);
        acc.y = fmaf(e0.y, a0.y, acc.y);
        acc.z = fmaf(e0.y, b0.x, acc.z);
        acc.w = fmaf(e0.y, b0.y, acc.w);
    }

    float sc = rsqrtf((float)max(end - beg, 1));
    float4 b = *reinterpret_cast<const float4*>(&bias[lane * 4]);
    acc.x = fmaf(acc.x, sc, b.x);
    acc.y = fmaf(acc.y, sc, b.y);
    acc.z = fmaf(acc.z, sc, b.z);
    acc.w = fmaf(acc.w, sc, b.w);
    *reinterpret_cast<float4*>(&out[node * KOUT + lane * 4]) = acc;
}

// ---------------------------------------------------------------------------
// Fork-join with valid capture semantics: fork event recorded on the capturing
// stream BEFORE any side-stream work; side stream joins capture via WaitEvent.
// ---------------------------------------------------------------------------
static cudaStream_t s_side = 0;
static cudaEvent_t  s_eFork = 0, s_eGemm = 0;

extern "C" void kernel_launch(void* const* d_in, const int* in_sizes, int n_in,
                              void* d_out, int out_size) {
    const float* feat   = (const float*)d_in[0];
    const int*   src    = (const int*)  d_in[1];
    const int*   dst    = (const int*)  d_in[2];
    const float* ew     = (const float*)d_in[3];
    const float* weight = (const float*)d_in[4];
    const float* bias   = (const float*)d_in[5];
    const float* maskr  = (const float*)d_in[6];
    float* out = (float*)d_out;

    if (!s_side) {
        cudaStreamCreateWithFlags(&s_side, cudaStreamNonBlocking);
        cudaEventCreateWithFlags(&s_eFork, cudaEventDisableTiming);
        cudaEventCreateWithFlags(&s_eGemm, cudaEventDisableTiming);
    }

    // fork: event on the capturing (default) stream, side stream waits on it
    cudaEventRecord(s_eFork, 0);
    cudaStreamWaitEvent(s_side, s_eFork, 0);

    // side stream: weight fp16 + GEMM (no degree dependency)
    k_wt<<<(KOUT * KIN + 255) / 256, 256, 0, s_side>>>(weight, maskr);
    k_gemm_mma<<<(NN + 127) / 128, 256, 0, s_side>>>(feat);
    cudaEventRecord(s_eGemm, s_side);

    // main stream: degrees + CSR build
    k_init<<<256, 256>>>();
    k_deg<<<(EE + 255) / 256, 256>>>(src, dst);
    k_scan1<<<NB_SCAN, 1024>>>();
    k_scan2<<<1, 128>>>();
    k_scan3<<<(NN + 255) / 256, 256>>>();
    k_bucket<<<(EE + 255) / 256, 256>>>(src, dst, ew);

    // join, then aggregate
    cudaStreamWaitEvent(0, s_eGemm, 0);
    k_agg<<<(NN + 7) / 8, 256>>>(out, bias);
}

// round 17
// speedup vs baseline: 1.2687x; 1.0383x over previous
#include <cuda_runtime.h>
#include <cuda_fp16.h>
#include <cstdint>

#define NN   100000
#define EE   1600000
#define KIN  256
#define KOUT 128
#define NB_SCAN ((NN + 1023) / 1024)   // 98

// Scratch (allocation-free rule: __device__ globals)
__device__ __half g_featproj[NN * KOUT];   // 25.6 MB projected features (fp16, UNSCALED)
__device__ float2 g_edges[EE];             // dst-bucketed (src_bits, w*outscale)
__device__ int    g_outcnt[NN];
__device__ int    g_incnt[NN];
__device__ int    g_scanpart[NN];
__device__ int    g_rowoff[NN + 1];
__device__ int    g_cursor[NN];
__device__ int    g_blocksum[NB_SCAN];
__device__ int    g_blockoff[NB_SCAN];
__device__ __half g_wt[KOUT * KIN];        // W^T fp16(rn)  [N=128][K=256]

// ---------------------------------------------------------------------------
__global__ void k_init() {
    int i = blockIdx.x * blockDim.x + threadIdx.x;
    int stride = gridDim.x * blockDim.x;
    for (int j = i; j < NN; j += stride) { g_outcnt[j] = 0; g_incnt[j] = 0; }
    if (i == 0) g_rowoff[NN] = EE;
}

// ---------------------------------------------------------------------------
__global__ void k_deg(const int* __restrict__ src, const int* __restrict__ dst) {
    int i = blockIdx.x * blockDim.x + threadIdx.x;
    if (i < EE) {
        atomicAdd(&g_outcnt[src[i]], 1);
        atomicAdd(&g_incnt[dst[i]], 1);
    }
}

// ---------------------------------------------------------------------------
// Exclusive scan of in-degrees (3 kernels)
// ---------------------------------------------------------------------------
__device__ __forceinline__ int warpInclScan(int v) {
#pragma unroll
    for (int o = 1; o < 32; o <<= 1) {
        int n = __shfl_up_sync(0xFFFFFFFFu, v, o);
        if ((threadIdx.x & 31) >= o) v += n;
    }
    return v;
}

__global__ __launch_bounds__(1024) void k_scan1() {
    __shared__ int ws[32];
    int tid = threadIdx.x;
    int i = blockIdx.x * 1024 + tid;
    int lane = tid & 31, wid = tid >> 5;
    int v = (i < NN) ? g_incnt[i] : 0;
    int inc = warpInclScan(v);
    if (lane == 31) ws[wid] = inc;
    __syncthreads();
    if (wid == 0) ws[lane] = warpInclScan(ws[lane]);
    __syncthreads();
    int excl = inc - v + (wid > 0 ? ws[wid - 1] : 0);
    if (i < NN) g_scanpart[i] = excl;
    if (tid == 1023) g_blocksum[blockIdx.x] = ws[31];
}

__global__ __launch_bounds__(128) void k_scan2() {
    __shared__ int ws[4];
    int tid = threadIdx.x;
    int lane = tid & 31, wid = tid >> 5;
    int v = (tid < NB_SCAN) ? g_blocksum[tid] : 0;
    int inc = warpInclScan(v);
    if (lane == 31) ws[wid] = inc;
    __syncthreads();
    if (wid == 0) {
        int w = (lane < 4) ? ws[lane] : 0;   // full warp runs the shfl scan
        w = warpInclScan(w);
        if (lane < 4) ws[lane] = w;
    }
    __syncthreads();
    int excl = inc - v + (wid > 0 ? ws[wid - 1] : 0);
    if (tid < NB_SCAN) g_blockoff[tid] = excl;
}

__global__ void k_scan3() {
    int i = blockIdx.x * blockDim.x + threadIdx.x;
    if (i < NN) {
        int off = g_scanpart[i] + g_blockoff[i >> 10];
        g_rowoff[i] = off;
        g_cursor[i] = off;
    }
}

// ---------------------------------------------------------------------------
// Bucket edges by dst; fold out_deg^-1/2 of src into the edge weight so the
// GEMM has no dependency on degrees (stream overlap from t=0).
// ---------------------------------------------------------------------------
__global__ void k_bucket(const int* __restrict__ src, const int* __restrict__ dst,
                         const float* __restrict__ ew) {
    int e = blockIdx.x * blockDim.x + threadIdx.x;
    if (e < EE) {
        int s = src[e];
        int d = dst[e];
        float w = ew[e] * rsqrtf((float)max(g_outcnt[s], 1));
        int pos = atomicAdd(&g_cursor[d], 1);
        g_edges[pos] = make_float2(__int_as_float(s), w);
    }
}

// ---------------------------------------------------------------------------
// Kernel: transpose + mask + fp16(rn) of the weight: W[K,N] -> Wt[N,K]
// ---------------------------------------------------------------------------
__global__ void k_wt(const float* __restrict__ weight, const float* __restrict__ maskr) {
    int i = blockIdx.x * blockDim.x + threadIdx.x;
    if (i >= KOUT * KIN) return;
    int n = i >> 8;          // 0..127
    int k = i & 255;         // 0..255
    float v = (maskr[k * KOUT + n] > 0.5f) ? weight[k * KOUT + n] : 0.f;
    g_wt[i] = __float2half_rn(v);
}

// ---------------------------------------------------------------------------
// Pure fp16 1-term tensor-core GEMM on mma.sync (HMMA), fp32 accumulation.
// featproj(fp16) = rn16(feat) @ rn16(maskedW).
// BM=128, BN=128, BK=32; 8 warps, warp tile 32x64. A-prefetch pipeline.
// ---------------------------------------------------------------------------
#define SSTR 40

__device__ __forceinline__ uint32_t smem_u32(const void* p) {
    uint32_t a;
    asm("{ .reg .u64 t; cvta.to.shared.u64 t, %1; cvt.u32.u64 %0, t; }"
        : "=r"(a) : "l"(p));
    return a;
}

__device__ __forceinline__ void ldm_x4(uint32_t* r, uint32_t addr) {
    asm volatile("ldmatrix.sync.aligned.m8n8.x4.shared.b16 {%0,%1,%2,%3}, [%4];"
                 : "=r"(r[0]), "=r"(r[1]), "=r"(r[2]), "=r"(r[3]) : "r"(addr));
}

__device__ __forceinline__ void mma_f16(float* c, const uint32_t* a, const uint32_t* b) {
    asm volatile(
        "mma.sync.aligned.m16n8k16.row.col.f32.f16.f16.f32 "
        "{%0,%1,%2,%3}, {%4,%5,%6,%7}, {%8,%9}, {%0,%1,%2,%3};"
        : "+f"(c[0]), "+f"(c[1]), "+f"(c[2]), "+f"(c[3])
        : "r"(a[0]), "r"(a[1]), "r"(a[2]), "r"(a[3]), "r"(b[0]), "r"(b[1]));
}

__global__ __launch_bounds__(256, 2) void k_gemm_mma(const float* __restrict__ feat) {
    __shared__ __half sA[128 * SSTR];
    __shared__ __half sB[128 * SSTR];

    const int tid = threadIdx.x;
    const int wid = tid >> 5, lane = tid & 31;
    const int blockRow = blockIdx.x * 128;

    const uint32_t uA = smem_u32(sA), uB = smem_u32(sB);

    const int mbase = (wid & 3) * 32;
    const int nbase = (wid >> 2) * 64;

    float acc[2][8][4];
#pragma unroll
    for (int m = 0; m < 2; m++)
#pragma unroll
        for (int n = 0; n < 8; n++)
#pragma unroll
            for (int q = 0; q < 4; q++) acc[m][n][q] = 0.f;

    const uint32_t aoff = (uint32_t)((lane & 15) * (SSTR * 2) + (lane >> 4) * 16);
    const uint32_t boff = (uint32_t)(((lane & 7) + ((lane >> 4) << 3)) * (SSTR * 2) +
                                     (((lane >> 3) & 1) << 4));

    // per-thread load mappings
    const int arow = tid >> 1;
    const int ach  = (tid & 1) * 16;
    const int grow = blockRow + arow;
    const float4* apbase = (grow < NN)
        ? reinterpret_cast<const float4*>(&feat[grow * KIN + ach]) : nullptr;
    const int bq = (tid & 1) * 2;
    const int asm_off = arow * SSTR + ach;      // A smem elem offset
    const int bsm_off = arow * SSTR + bq * 8;   // B smem elem offset

    // prologue: prefetch chunk 0 of A
    float4 pa[4];
#pragma unroll
    for (int j = 0; j < 4; j++)
        pa[j] = apbase ? apbase[j] : make_float4(0.f, 0.f, 0.f, 0.f);

    for (int c = 0; c < 8; c++) {
        const int k0 = c * 32;

        // ---- store stage: A rn-fp16 pack from prefetched regs
#pragma unroll
        for (int j = 0; j < 4; j++) {
            __half2 h0 = __floats2half2_rn(pa[j].x, pa[j].y);
            __half2 h1 = __floats2half2_rn(pa[j].z, pa[j].w);
            int o = asm_off + j * 4;
            *reinterpret_cast<uint2*>(&sA[o]) =
                make_uint2(*reinterpret_cast<uint32_t*>(&h0),
                           *reinterpret_cast<uint32_t*>(&h1));
        }
        // ---- B (single fp16 buffer) from L2-resident g_wt
        {
            uint4 b0 = *reinterpret_cast<const uint4*>(&g_wt[arow * KIN + k0 + bq * 8]);
            uint4 b1 = *reinterpret_cast<const uint4*>(&g_wt[arow * KIN + k0 + (bq + 1) * 8]);
            *reinterpret_cast<uint4*>(&sB[bsm_off])     = b0;
            *reinterpret_cast<uint4*>(&sB[bsm_off + 8]) = b1;
        }
        __syncthreads();

        // ---- prefetch next chunk's A (DRAM latency hides under MMAs below)
        if (c < 7) {
            const float4* ap = apbase ? apbase + (c + 1) * 8 : nullptr;
#pragma unroll
            for (int j = 0; j < 4; j++)
                pa[j] = ap ? ap[j] : make_float4(0.f, 0.f, 0.f, 0.f);
        }

        // ---- MMA stage: single term
#pragma unroll
        for (int ks = 0; ks < 2; ks++) {
            const uint32_t kb = (uint32_t)(ks * 16 * 2);

            uint32_t a[2][4];
#pragma unroll
            for (int mt = 0; mt < 2; mt++) {
                uint32_t ab = (uint32_t)((mbase + mt * 16) * (SSTR * 2)) + kb + aoff;
                ldm_x4(a[mt], uA + ab);
            }
#pragma unroll
            for (int p = 0; p < 4; p++) {
                uint32_t bb = (uint32_t)((nbase + p * 16) * (SSTR * 2)) + kb + boff;
                uint32_t rb[4];
                ldm_x4(rb, uB + bb);
#pragma unroll
                for (int mt = 0; mt < 2; mt++) {
                    mma_f16(acc[mt][2 * p],     a[mt], rb);
                    mma_f16(acc[mt][2 * p + 1], a[mt], rb + 2);
                }
            }
        }
        __syncthreads();
    }

    // Epilogue: store fp16 result
#pragma unroll
    for (int mt = 0; mt < 2; mt++) {
        int r0 = blockRow + mbase + mt * 16 + (lane >> 2);
        int r1 = r0 + 8;
#pragma unroll
        for (int nt = 0; nt < 8; nt++) {
            int col = nbase + nt * 8 + (lane & 3) * 2;
            if (r0 < NN)
                *reinterpret_cast<__half2*>(&g_featproj[r0 * KOUT + col]) =
                    __floats2half2_rn(acc[mt][nt][0], acc[mt][nt][1]);
            if (r1 < NN)
                *reinterpret_cast<__half2*>(&g_featproj[r1 * KOUT + col]) =
                    __floats2half2_rn(acc[mt][nt][2], acc[mt][nt][3]);
        }
    }
}

// ---------------------------------------------------------------------------
// Kernel: aggregation. One warp per dst node; fp16 gathers (256B/edge-warp),
// fp32 accumulation, fused in_deg^-1/2 + bias. No fp atomics.
// ---------------------------------------------------------------------------
__global__ __launch_bounds__(256) void k_agg(float* __restrict__ out,
                                             const float* __restrict__ bias) {
    int node = blockIdx.x * 8 + (threadIdx.x >> 5);
    int lane = threadIdx.x & 31;
    if (node >= NN) return;

    int beg = g_rowoff[node];
    int end = g_rowoff[node + 1];

    float4 acc = make_float4(0.f, 0.f, 0.f, 0.f);
    int e = beg;
    for (; e + 1 < end; e += 2) {
        float2 e0 = g_edges[e];
        float2 e1 = g_edges[e + 1];
        int s0 = __float_as_int(e0.x);
        int s1 = __float_as_int(e1.x);
        uint2 q0 = *reinterpret_cast<const uint2*>(&g_featproj[s0 * KOUT + lane * 4]);
        uint2 q1 = *reinterpret_cast<const uint2*>(&g_featproj[s1 * KOUT + lane * 4]);
        float2 a0 = __half22float2(*reinterpret_cast<__half2*>(&q0.x));
        float2 b0 = __half22float2(*reinterpret_cast<__half2*>(&q0.y));
        float2 a1 = __half22float2(*reinterpret_cast<__half2*>(&q1.x));
        float2 b1 = __half22float2(*reinterpret_cast<__half2*>(&q1.y));
        acc.x = fmaf(e0.y, a0.x, fmaf(e1.y, a1.x, acc.x));
        acc.y = fmaf(e0.y, a0.y, fmaf(e1.y, a1.y, acc.y));
        acc.z = fmaf(e0.y, b0.x, fmaf(e1.y, b1.x, acc.z));
        acc.w = fmaf(e0.y, b0.y, fmaf(e1.y, b1.y, acc.w));
    }
    if (e < end) {
        float2 e0 = g_edges[e];
        int s0 = __float_as_int(e0.x);
        uint2 q0 = *reinterpret_cast<const uint2*>(&g_featproj[s0 * KOUT + lane * 4]);
        float2 a0 = __half22float2(*reinterpret_cast<__half2*>(&q0.x));
        float2 b0 = __half22float2(*reinterpret_cast<__half2*>(&q0.y));
        acc.x = fmaf(e0.y, a0.x, acc.x);
        acc.y = fmaf(e0.y, a0.y, acc.y);
        acc.z = fmaf(e0.y, b0.x, acc.z);
        acc.w = fmaf(e0.y, b0.y, acc.w);
    }

    float sc = rsqrtf((float)max(end - beg, 1));
    float4 b = *reinterpret_cast<const float4*>(&bias[lane * 4]);
    acc.x = fmaf(acc.x, sc, b.x);
    acc.y = fmaf(acc.y, sc, b.y);
    acc.z = fmaf(acc.z, sc, b.z);
    acc.w = fmaf(acc.w, sc, b.w);
    *reinterpret_cast<float4*>(&out[node * KOUT + lane * 4]) = acc;
}

// ---------------------------------------------------------------------------
// Fork-join with valid capture semantics: fork event recorded on the capturing
// stream BEFORE any side-stream work; side stream joins capture via WaitEvent.
// ---------------------------------------------------------------------------
static cudaStream_t s_side = 0;
static cudaEvent_t  s_eFork = 0, s_eGemm = 0;

extern "C" void kernel_launch(void* const* d_in, const int* in_sizes, int n_in,
                              void* d_out, int out_size) {
    const float* feat   = (const float*)d_in[0];
    const int*   src    = (const int*)  d_in[1];
    const int*   dst    = (const int*)  d_in[2];
    const float* ew     = (const float*)d_in[3];
    const float* weight = (const float*)d_in[4];
    const float* bias   = (const float*)d_in[5];
    const float* maskr  = (const float*)d_in[6];
    float* out = (float*)d_out;

    if (!s_side) {
        cudaStreamCreateWithFlags(&s_side, cudaStreamNonBlocking);
        cudaEventCreateWithFlags(&s_eFork, cudaEventDisableTiming);
        cudaEventCreateWithFlags(&s_eGemm, cudaEventDisableTiming);
    }

    // fork: event on the capturing (default) stream, side stream waits on it
    cudaEventRecord(s_eFork, 0);
    cudaStreamWaitEvent(s_side, s_eFork, 0);

    // side stream: weight fp16 + GEMM (no degree dependency)
    k_wt<<<(KOUT * KIN + 255) / 256, 256, 0, s_side>>>(weight, maskr);
    k_gemm_mma<<<(NN + 127) / 128, 256, 0, s_side>>>(feat);
    cudaEventRecord(s_eGemm, s_side);

    // main stream: degrees + CSR build
    k_init<<<256, 256>>>();
    k_deg<<<(EE + 255) / 256, 256>>>(src, dst);
    k_scan1<<<NB_SCAN, 1024>>>();
    k_scan2<<<1, 128>>>();
    k_scan3<<<(NN + 255) / 256, 256>>>();
    k_bucket<<<(EE + 255) / 256, 256>>>(src, dst, ew);

    // join, then aggregate
    cudaStreamWaitEvent(0, s_eGemm, 0);
    k_agg<<<(NN + 7) / 8, 256>>>(out, bias);
}